// round 9
// baseline (speedup 1.0000x reference)
#include <cuda_runtime.h>

// Differential box-counting fractal dimension, 512x512 f32, 64x64 windows
// stride 4 -> 113x113. One block per OUTPUT ROW (113 blocks = one wave).
// 3 phases / 2 barriers:
//   P1: packed (max,min) 4x4-pixel-tile grid D0 (16x128), MLP-8 batched loads
//   B : cs0 (16ld), cs1 pair-split (16ld), cs2 pair-split (32ld),
//       V3 vertical 8-row max/min (8ld)  -- balanced, all <=32 loads
//   P6: per-window horizontal sums; d32/d64 horizontal 8-max folded here.

#define OH 113

__global__ __launch_bounds__(1024, 1)
void fd_kernel(const float* __restrict__ img, float* __restrict__ out)
{
    __shared__ float2 D0[16][128];     // (max, min) per 4x4 pixel tile
    __shared__ float2 V3[2][128];      // vertical 8-row (max, min), rows {0..7},{8..15}
    __shared__ float  cs0[128], cs1[128], cs2[128];

    const int tid = threadIdx.x;
    const int gi  = blockIdx.x;        // output row 0..112
    const int R0  = 4 * gi;

    // ---- P1: 4x4 pixel-tile max/min, 2 tiles/thread, 8 batched LDG.128 ----
    {
        const int r = tid >> 7, c = tid & 127;
        const float* pA = img + (R0 + 4 * r) * 512 + 4 * c;
        const float* pB = pA + 32 * 512;
        float4 v0 = *reinterpret_cast<const float4*>(pA);
        float4 v1 = *reinterpret_cast<const float4*>(pA + 512);
        float4 v2 = *reinterpret_cast<const float4*>(pA + 1024);
        float4 v3 = *reinterpret_cast<const float4*>(pA + 1536);
        float4 w0 = *reinterpret_cast<const float4*>(pB);
        float4 w1 = *reinterpret_cast<const float4*>(pB + 512);
        float4 w2 = *reinterpret_cast<const float4*>(pB + 1024);
        float4 w3 = *reinterpret_cast<const float4*>(pB + 1536);

        float mxA = fmaxf(fmaxf(v0.x, v0.y), fmaxf(v0.z, v0.w));
        float mnA = fminf(fminf(v0.x, v0.y), fminf(v0.z, v0.w));
        mxA = fmaxf(mxA, fmaxf(fmaxf(v1.x, v1.y), fmaxf(v1.z, v1.w)));
        mnA = fminf(mnA, fminf(fminf(v1.x, v1.y), fminf(v1.z, v1.w)));
        mxA = fmaxf(mxA, fmaxf(fmaxf(v2.x, v2.y), fmaxf(v2.z, v2.w)));
        mnA = fminf(mnA, fminf(fminf(v2.x, v2.y), fminf(v2.z, v2.w)));
        mxA = fmaxf(mxA, fmaxf(fmaxf(v3.x, v3.y), fmaxf(v3.z, v3.w)));
        mnA = fminf(mnA, fminf(fminf(v3.x, v3.y), fminf(v3.z, v3.w)));

        float mxB = fmaxf(fmaxf(w0.x, w0.y), fmaxf(w0.z, w0.w));
        float mnB = fminf(fminf(w0.x, w0.y), fminf(w0.z, w0.w));
        mxB = fmaxf(mxB, fmaxf(fmaxf(w1.x, w1.y), fmaxf(w1.z, w1.w)));
        mnB = fminf(mnB, fminf(fminf(w1.x, w1.y), fminf(w1.z, w1.w)));
        mxB = fmaxf(mxB, fmaxf(fmaxf(w2.x, w2.y), fmaxf(w2.z, w2.w)));
        mnB = fminf(mnB, fminf(fminf(w2.x, w2.y), fminf(w2.z, w2.w)));
        mxB = fmaxf(mxB, fmaxf(fmaxf(w3.x, w3.y), fmaxf(w3.z, w3.w)));
        mnB = fminf(mnB, fminf(fminf(w3.x, w3.y), fminf(w3.z, w3.w)));

        D0[r][c]     = make_float2(mxA, mnA);
        D0[r + 8][c] = make_float2(mxB, mnB);
    }
    __syncthreads();

    // ---- Phase B: balanced vertical reductions ----
    if (tid < 128) {
        // cs0[c] = sum over 16 rows of (max - min)          [16 loads]
        const int c = tid;
        float s = 0.f;
        #pragma unroll
        for (int r = 0; r < 16; r++) {
            const float2 v = D0[r][c];
            s += v.x - v.y;
        }
        cs0[c] = s;
    } else if (tid < 384) {
        // cs1[c]: pair-split over a-halves                  [16 loads]
        const int idx = tid - 128;
        const int c = idx >> 1, h = idx & 1;
        const int c1 = (c + 1 < 128) ? c + 1 : 127;   // clamp; cs1[>=127] unused
        float s = 0.f;
        #pragma unroll
        for (int aa = 0; aa < 4; aa++) {
            const int a = 4 * h + aa;
            const float2 v00 = D0[2*a][c],   v01 = D0[2*a][c1];
            const float2 v10 = D0[2*a+1][c], v11 = D0[2*a+1][c1];
            s += fmaxf(fmaxf(v00.x, v01.x), fmaxf(v10.x, v11.x))
               - fminf(fminf(v00.y, v01.y), fminf(v10.y, v11.y));
        }
        s += __shfl_xor_sync(0xffffffffu, s, 1);
        if (h == 0) cs1[c] = s;
    } else if (tid < 640) {
        // cs2[c]: pair-split over a-halves                  [32 loads]
        const int idx = tid - 384;
        const int c = idx >> 1, h = idx & 1;
        const int cc0 = c;
        const int cc1 = (c + 1 < 128) ? c + 1 : 127;  // clamp; cs2[>=125] unused
        const int cc2 = (c + 2 < 128) ? c + 2 : 127;
        const int cc3 = (c + 3 < 128) ? c + 3 : 127;
        float s = 0.f;
        #pragma unroll
        for (int aa = 0; aa < 2; aa++) {
            const int rb = 4 * (2 * h + aa);
            float m = -3.0e38f, n = 3.0e38f;
            #pragma unroll
            for (int dr = 0; dr < 4; dr++) {
                const float2 a0 = D0[rb+dr][cc0], a1 = D0[rb+dr][cc1];
                const float2 a2 = D0[rb+dr][cc2], a3 = D0[rb+dr][cc3];
                m = fmaxf(m, fmaxf(fmaxf(a0.x, a1.x), fmaxf(a2.x, a3.x)));
                n = fminf(n, fminf(fminf(a0.y, a1.y), fminf(a2.y, a3.y)));
            }
            s += m - n;
        }
        s += __shfl_xor_sync(0xffffffffu, s, 1);
        if (h == 0) cs2[c] = s;
    } else if (tid < 896) {
        // V3[j][c] = vertical max/min over 8 rows           [8 loads]
        const int idx = tid - 640;
        const int j = idx >> 7, c = idx & 127;
        float m = -3.0e38f, n = 3.0e38f;
        #pragma unroll
        for (int dr = 0; dr < 8; dr++) {
            const float2 v = D0[8*j + dr][c];
            m = fmaxf(m, v.x);
            n = fminf(n, v.y);
        }
        V3[j][c] = make_float2(m, n);
    }
    __syncthreads();

    // ---- P6: per-window sums + regression (113 threads) ----
    if (tid < OH) {
        const int wj = tid;
        float d4 = 0.f, d8 = 0.f, d16 = 0.f;
        #pragma unroll
        for (int t = 0; t < 16; t++) d4  += cs0[wj + t];
        #pragma unroll
        for (int b = 0; b < 8;  b++) d8  += cs1[wj + 2 * b];
        #pragma unroll
        for (int b = 0; b < 4;  b++) d16 += cs2[wj + 4 * b];

        // d32: four 8x8 quadrants from V3 (horizontal 8-max); d64 global.
        float d32 = 0.f, gm = -3.0e38f, gn = 3.0e38f;
        #pragma unroll
        for (int j = 0; j < 2; j++) {
            #pragma unroll
            for (int k = 0; k < 2; k++) {
                float m = -3.0e38f, n = 3.0e38f;
                #pragma unroll
                for (int t = 0; t < 8; t++) {
                    const float2 v = V3[j][wj + 8 * k + t];
                    m = fmaxf(m, v.x);
                    n = fminf(n, v.y);
                }
                d32 += m - n;
                gm = fmaxf(gm, m);
                gn = fminf(gn, n);
            }
        }
        const float d64 = gm - gn;

        const float ls0 = 4.15888308336f;   // ln 64
        const float ls1 = 3.46573590280f;   // ln 32
        const float ls2 = 2.77258872224f;   // ln 16
        const float ls3 = 2.07944154168f;   // ln 8
        const float ls4 = 1.38629436112f;   // ln 4
        const float S2  = ls0*ls0 + ls1*ls1 + ls2*ls2 + ls3*ls3 + ls4*ls4;
        const float num = ls0 * __logf(d64) + ls1 * __logf(d32)
                        + ls2 * __logf(d16) + ls3 * __logf(d8)
                        + ls4 * __logf(d4);
        out[gi * OH + wj] = -num / S2;
    }
}

extern "C" void kernel_launch(void* const* d_in, const int* in_sizes, int n_in,
                              void* d_out, int out_size)
{
    const float* img = (const float*)d_in[0];   // (1,1,512,512) f32
    float* out = (float*)d_out;                 // (1,1,113,113) f32
    fd_kernel<<<OH, 1024>>>(img, out);
}

// round 10
// speedup vs baseline: 1.0792x; 1.0792x over previous
#include <cuda_runtime.h>

// Differential box-counting fractal dimension, 512x512 f32, 64x64 windows
// stride 4 -> 113x113. One block per OUTPUT ROW (113 blocks = one wave).
// 3 phases / 2 barriers, all phase-B threads <=16 shared loads:
//   P1: packed (max,min) 4x4-pixel-tile grid D0 (16x128), 2x4 batched loads
//   B : cs0 (16ld) | cs1 2-way partials (16ld) | cs2 4-way partials (16ld)
//       | V3 both 8-row halves as float4 (16ld)     -- 1024 threads exactly
//   P6: per-window horizontal sums over partials + regression.

#define OH 113

__global__ __launch_bounds__(1024, 1)
void fd_kernel(const float* __restrict__ img, float* __restrict__ out)
{
    __shared__ float2 D0[16][128];   // (max, min) per 4x4 pixel tile
    __shared__ float  cs0[128];      // level-4 column diffs (16 rows)
    __shared__ float  cs1p[2][128];  // level-8 column partials (a=4h..4h+3)
    __shared__ float  cs2p[4][128];  // level-16 column partials (one a-block)
    __shared__ float4 V3b[128];      // (max0,min0,max1,min1): vertical 8-row halves

    const int tid = threadIdx.x;
    const int gi  = blockIdx.x;      // output row 0..112
    const int R0  = 4 * gi;

    // ---- P1: 4x4 pixel-tile max/min, 2 tiles/thread, two 4-load batches ----
    {
        const int r = tid >> 7, c = tid & 127;
        const float* pA = img + (R0 + 4 * r) * 512 + 4 * c;
        {
            float4 v0 = *reinterpret_cast<const float4*>(pA);
            float4 v1 = *reinterpret_cast<const float4*>(pA + 512);
            float4 v2 = *reinterpret_cast<const float4*>(pA + 1024);
            float4 v3 = *reinterpret_cast<const float4*>(pA + 1536);
            float mx = fmaxf(fmaxf(v0.x, v0.y), fmaxf(v0.z, v0.w));
            float mn = fminf(fminf(v0.x, v0.y), fminf(v0.z, v0.w));
            mx = fmaxf(mx, fmaxf(fmaxf(v1.x, v1.y), fmaxf(v1.z, v1.w)));
            mn = fminf(mn, fminf(fminf(v1.x, v1.y), fminf(v1.z, v1.w)));
            mx = fmaxf(mx, fmaxf(fmaxf(v2.x, v2.y), fmaxf(v2.z, v2.w)));
            mn = fminf(mn, fminf(fminf(v2.x, v2.y), fminf(v2.z, v2.w)));
            mx = fmaxf(mx, fmaxf(fmaxf(v3.x, v3.y), fmaxf(v3.z, v3.w)));
            mn = fminf(mn, fminf(fminf(v3.x, v3.y), fminf(v3.z, v3.w)));
            D0[r][c] = make_float2(mx, mn);
        }
        const float* pB = pA + 32 * 512;
        {
            float4 v0 = *reinterpret_cast<const float4*>(pB);
            float4 v1 = *reinterpret_cast<const float4*>(pB + 512);
            float4 v2 = *reinterpret_cast<const float4*>(pB + 1024);
            float4 v3 = *reinterpret_cast<const float4*>(pB + 1536);
            float mx = fmaxf(fmaxf(v0.x, v0.y), fmaxf(v0.z, v0.w));
            float mn = fminf(fminf(v0.x, v0.y), fminf(v0.z, v0.w));
            mx = fmaxf(mx, fmaxf(fmaxf(v1.x, v1.y), fmaxf(v1.z, v1.w)));
            mn = fminf(mn, fminf(fminf(v1.x, v1.y), fminf(v1.z, v1.w)));
            mx = fmaxf(mx, fmaxf(fmaxf(v2.x, v2.y), fmaxf(v2.z, v2.w)));
            mn = fminf(mn, fminf(fminf(v2.x, v2.y), fminf(v2.z, v2.w)));
            mx = fmaxf(mx, fmaxf(fmaxf(v3.x, v3.y), fmaxf(v3.z, v3.w)));
            mn = fminf(mn, fminf(fminf(v3.x, v3.y), fminf(v3.z, v3.w)));
            D0[r + 8][c] = make_float2(mx, mn);
        }
    }
    __syncthreads();

    // ---- Phase B: all branches <= 16 shared loads ----
    if (tid < 128) {
        // cs0[c] = sum over 16 rows of (max - min)
        const int c = tid;
        float s = 0.f;
        #pragma unroll
        for (int r = 0; r < 16; r++) {
            const float2 v = D0[r][c];
            s += v.x - v.y;
        }
        cs0[c] = s;
    } else if (tid < 384) {
        // cs1p[h][c]: 4 of 8 2x2-blocks (a = 4h..4h+3)
        const int idx = tid - 128;
        const int h = idx >> 7, c = idx & 127;
        if (c < 127) {
            float s = 0.f;
            #pragma unroll
            for (int aa = 0; aa < 4; aa++) {
                const int a = 4 * h + aa;
                const float2 v00 = D0[2*a][c],   v01 = D0[2*a][c+1];
                const float2 v10 = D0[2*a+1][c], v11 = D0[2*a+1][c+1];
                s += fmaxf(fmaxf(v00.x, v01.x), fmaxf(v10.x, v11.x))
                   - fminf(fminf(v00.y, v01.y), fminf(v10.y, v11.y));
            }
            cs1p[h][c] = s;
        }
    } else if (tid < 896) {
        // cs2p[a][c]: one 4x4 block diff
        const int idx = tid - 384;
        const int a = idx >> 7, c = idx & 127;
        if (c < 125) {
            const int rb = 4 * a;
            float m = -3.0e38f, n = 3.0e38f;
            #pragma unroll
            for (int dr = 0; dr < 4; dr++) {
                const float2 a0 = D0[rb+dr][c],   a1 = D0[rb+dr][c+1];
                const float2 a2 = D0[rb+dr][c+2], a3 = D0[rb+dr][c+3];
                m = fmaxf(m, fmaxf(fmaxf(a0.x, a1.x), fmaxf(a2.x, a3.x)));
                n = fminf(n, fminf(fminf(a0.y, a1.y), fminf(a2.y, a3.y)));
            }
            cs2p[a][c] = m - n;
        }
    } else {
        // V3b[c] = (max rows0-7, min rows0-7, max rows8-15, min rows8-15)
        const int c = tid - 896;
        float m0 = -3.0e38f, n0 = 3.0e38f, m1 = -3.0e38f, n1 = 3.0e38f;
        #pragma unroll
        for (int dr = 0; dr < 8; dr++) {
            const float2 v0 = D0[dr][c];
            const float2 v1 = D0[8 + dr][c];
            m0 = fmaxf(m0, v0.x);  n0 = fminf(n0, v0.y);
            m1 = fmaxf(m1, v1.x);  n1 = fminf(n1, v1.y);
        }
        V3b[c] = make_float4(m0, n0, m1, n1);
    }
    __syncthreads();

    // ---- P6: per-window sums + regression (113 threads) ----
    if (tid < OH) {
        const int wj = tid;
        float d4 = 0.f, d8 = 0.f, d16 = 0.f;
        #pragma unroll
        for (int t = 0; t < 16; t++) d4 += cs0[wj + t];
        #pragma unroll
        for (int b = 0; b < 8; b++) {
            const int c = wj + 2 * b;
            d8 += cs1p[0][c] + cs1p[1][c];
        }
        #pragma unroll
        for (int b = 0; b < 4; b++) {
            const int c = wj + 4 * b;
            d16 += cs2p[0][c] + cs2p[1][c] + cs2p[2][c] + cs2p[3][c];
        }

        // d32: four 8x8 quadrants (horizontal 8-wide max over V3b); d64 global.
        float d32 = 0.f, gm = -3.0e38f, gn = 3.0e38f;
        #pragma unroll
        for (int k = 0; k < 2; k++) {
            float m0 = -3.0e38f, n0 = 3.0e38f, m1 = -3.0e38f, n1 = 3.0e38f;
            #pragma unroll
            for (int t = 0; t < 8; t++) {
                const float4 v = V3b[wj + 8 * k + t];
                m0 = fmaxf(m0, v.x);  n0 = fminf(n0, v.y);
                m1 = fmaxf(m1, v.z);  n1 = fminf(n1, v.w);
            }
            d32 += (m0 - n0) + (m1 - n1);
            gm = fmaxf(gm, fmaxf(m0, m1));
            gn = fminf(gn, fminf(n0, n1));
        }
        const float d64 = gm - gn;

        const float ls0 = 4.15888308336f;   // ln 64
        const float ls1 = 3.46573590280f;   // ln 32
        const float ls2 = 2.77258872224f;   // ln 16
        const float ls3 = 2.07944154168f;   // ln 8
        const float ls4 = 1.38629436112f;   // ln 4
        const float S2  = ls0*ls0 + ls1*ls1 + ls2*ls2 + ls3*ls3 + ls4*ls4;
        const float num = ls0 * __logf(d64) + ls1 * __logf(d32)
                        + ls2 * __logf(d16) + ls3 * __logf(d8)
                        + ls4 * __logf(d4);
        out[gi * OH + wj] = -num / S2;
    }
}

extern "C" void kernel_launch(void* const* d_in, const int* in_sizes, int n_in,
                              void* d_out, int out_size)
{
    const float* img = (const float*)d_in[0];   // (1,1,512,512) f32
    float* out = (float*)d_out;                 // (1,1,113,113) f32
    fd_kernel<<<OH, 1024>>>(img, out);
}

// round 11
// speedup vs baseline: 1.2573x; 1.1650x over previous
#include <cuda_runtime.h>

// Differential box-counting fractal dimension, 512x512 f32, 64x64 windows
// stride 4 -> 113x113. One block per OUTPUT ROW (113 blocks = one wave).
// 3 phases / 2 barriers:
//   P1: packed (max,min) 4x4-pixel-tile grid D0 (16x128), 2x4 batched loads
//   B : cs0 (16ld) | cs1 2-way partials (16ld) | cs2 4-way partials (16ld)
//       | V3 both 8-row halves as float4 (16ld)   -- 1024 threads exactly
//   P6: windows split across intra-warp thread pairs (h=0: d4,d8 + 2 logs;
//       h=1: d16,d32,d64 + 3 logs), combined with one shfl_xor.

#define OH 113

__global__ __launch_bounds__(1024, 1)
void fd_kernel(const float* __restrict__ img, float* __restrict__ out)
{
    __shared__ float2 D0[16][128];   // (max, min) per 4x4 pixel tile
    __shared__ float  cs0[128];      // level-4 column diffs (16 rows)
    __shared__ float  cs1p[2][128];  // level-8 column partials (a=4h..4h+3)
    __shared__ float  cs2p[4][128];  // level-16 column partials (one a-block)
    __shared__ float4 V3b[128];      // (max0,min0,max1,min1): vertical 8-row halves

    const int tid = threadIdx.x;
    const int gi  = blockIdx.x;      // output row 0..112
    const int R0  = 4 * gi;

    // ---- P1: 4x4 pixel-tile max/min, 2 tiles/thread, two 4-load batches ----
    {
        const int r = tid >> 7, c = tid & 127;
        const float* pA = img + (R0 + 4 * r) * 512 + 4 * c;
        {
            float4 v0 = *reinterpret_cast<const float4*>(pA);
            float4 v1 = *reinterpret_cast<const float4*>(pA + 512);
            float4 v2 = *reinterpret_cast<const float4*>(pA + 1024);
            float4 v3 = *reinterpret_cast<const float4*>(pA + 1536);
            float mx = fmaxf(fmaxf(v0.x, v0.y), fmaxf(v0.z, v0.w));
            float mn = fminf(fminf(v0.x, v0.y), fminf(v0.z, v0.w));
            mx = fmaxf(mx, fmaxf(fmaxf(v1.x, v1.y), fmaxf(v1.z, v1.w)));
            mn = fminf(mn, fminf(fminf(v1.x, v1.y), fminf(v1.z, v1.w)));
            mx = fmaxf(mx, fmaxf(fmaxf(v2.x, v2.y), fmaxf(v2.z, v2.w)));
            mn = fminf(mn, fminf(fminf(v2.x, v2.y), fminf(v2.z, v2.w)));
            mx = fmaxf(mx, fmaxf(fmaxf(v3.x, v3.y), fmaxf(v3.z, v3.w)));
            mn = fminf(mn, fminf(fminf(v3.x, v3.y), fminf(v3.z, v3.w)));
            D0[r][c] = make_float2(mx, mn);
        }
        const float* pB = pA + 32 * 512;
        {
            float4 v0 = *reinterpret_cast<const float4*>(pB);
            float4 v1 = *reinterpret_cast<const float4*>(pB + 512);
            float4 v2 = *reinterpret_cast<const float4*>(pB + 1024);
            float4 v3 = *reinterpret_cast<const float4*>(pB + 1536);
            float mx = fmaxf(fmaxf(v0.x, v0.y), fmaxf(v0.z, v0.w));
            float mn = fminf(fminf(v0.x, v0.y), fminf(v0.z, v0.w));
            mx = fmaxf(mx, fmaxf(fmaxf(v1.x, v1.y), fmaxf(v1.z, v1.w)));
            mn = fminf(mn, fminf(fminf(v1.x, v1.y), fminf(v1.z, v1.w)));
            mx = fmaxf(mx, fmaxf(fmaxf(v2.x, v2.y), fmaxf(v2.z, v2.w)));
            mn = fminf(mn, fminf(fminf(v2.x, v2.y), fminf(v2.z, v2.w)));
            mx = fmaxf(mx, fmaxf(fmaxf(v3.x, v3.y), fmaxf(v3.z, v3.w)));
            mn = fminf(mn, fminf(fminf(v3.x, v3.y), fminf(v3.z, v3.w)));
            D0[r + 8][c] = make_float2(mx, mn);
        }
    }
    __syncthreads();

    // ---- Phase B: all branches <= 16 shared loads ----
    if (tid < 128) {
        const int c = tid;
        float s = 0.f;
        #pragma unroll
        for (int r = 0; r < 16; r++) {
            const float2 v = D0[r][c];
            s += v.x - v.y;
        }
        cs0[c] = s;
    } else if (tid < 384) {
        // cs1p[h][c]: 4 of 8 2x2-blocks (a = 4h..4h+3)
        const int idx = tid - 128;
        const int h = idx >> 7, c = idx & 127;
        if (c < 127) {
            float s = 0.f;
            #pragma unroll
            for (int aa = 0; aa < 4; aa++) {
                const int a = 4 * h + aa;
                const float2 v00 = D0[2*a][c],   v01 = D0[2*a][c+1];
                const float2 v10 = D0[2*a+1][c], v11 = D0[2*a+1][c+1];
                s += fmaxf(fmaxf(v00.x, v01.x), fmaxf(v10.x, v11.x))
                   - fminf(fminf(v00.y, v01.y), fminf(v10.y, v11.y));
            }
            cs1p[h][c] = s;
        }
    } else if (tid < 896) {
        // cs2p[a][c]: one 4x4 block diff
        const int idx = tid - 384;
        const int a = idx >> 7, c = idx & 127;
        if (c < 125) {
            const int rb = 4 * a;
            float m = -3.0e38f, n = 3.0e38f;
            #pragma unroll
            for (int dr = 0; dr < 4; dr++) {
                const float2 a0 = D0[rb+dr][c],   a1 = D0[rb+dr][c+1];
                const float2 a2 = D0[rb+dr][c+2], a3 = D0[rb+dr][c+3];
                m = fmaxf(m, fmaxf(fmaxf(a0.x, a1.x), fmaxf(a2.x, a3.x)));
                n = fminf(n, fminf(fminf(a0.y, a1.y), fminf(a2.y, a3.y)));
            }
            cs2p[a][c] = m - n;
        }
    } else {
        // V3b[c] = (max rows0-7, min rows0-7, max rows8-15, min rows8-15)
        const int c = tid - 896;
        float m0 = -3.0e38f, n0 = 3.0e38f, m1 = -3.0e38f, n1 = 3.0e38f;
        #pragma unroll
        for (int dr = 0; dr < 8; dr++) {
            const float2 v0 = D0[dr][c];
            const float2 v1 = D0[8 + dr][c];
            m0 = fmaxf(m0, v0.x);  n0 = fminf(n0, v0.y);
            m1 = fmaxf(m1, v1.x);  n1 = fminf(n1, v1.y);
        }
        V3b[c] = make_float4(m0, n0, m1, n1);
    }
    __syncthreads();

    // ---- P6: 2 threads per window (intra-warp pair), shfl combine ----
    if (tid < 2 * OH) {
        const int wj = tid >> 1;         // window 0..112
        const int h  = tid & 1;          // half id (pair lanes adjacent in warp)
        float part;

        if (h == 0) {
            float d4 = 0.f, d8 = 0.f;
            #pragma unroll
            for (int t = 0; t < 16; t++) d4 += cs0[wj + t];
            #pragma unroll
            for (int b = 0; b < 8; b++) {
                const int c = wj + 2 * b;
                d8 += cs1p[0][c] + cs1p[1][c];
            }
            // ln8 * log(d8) + ln4 * log(d4)
            part = 2.07944154168f * __logf(d8) + 1.38629436112f * __logf(d4);
        } else {
            float d16 = 0.f;
            #pragma unroll
            for (int b = 0; b < 4; b++) {
                const int c = wj + 4 * b;
                d16 += cs2p[0][c] + cs2p[1][c] + cs2p[2][c] + cs2p[3][c];
            }
            float d32 = 0.f, gm = -3.0e38f, gn = 3.0e38f;
            #pragma unroll
            for (int k = 0; k < 2; k++) {
                float m0 = -3.0e38f, n0 = 3.0e38f, m1 = -3.0e38f, n1 = 3.0e38f;
                #pragma unroll
                for (int t = 0; t < 8; t++) {
                    const float4 v = V3b[wj + 8 * k + t];
                    m0 = fmaxf(m0, v.x);  n0 = fminf(n0, v.y);
                    m1 = fmaxf(m1, v.z);  n1 = fminf(n1, v.w);
                }
                d32 += (m0 - n0) + (m1 - n1);
                gm = fmaxf(gm, fmaxf(m0, m1));
                gn = fminf(gn, fminf(n0, n1));
            }
            const float d64 = gm - gn;
            // ln64 * log(d64) + ln32 * log(d32) + ln16 * log(d16)
            part = 4.15888308336f * __logf(d64) + 3.46573590280f * __logf(d32)
                 + 2.77258872224f * __logf(d16);
        }

        const float other = __shfl_xor_sync(0xffffffffu, part, 1);
        if (h == 0) {
            // S2 = sum of ln(s)^2 for s in {64,32,16,8,4}
            const float S2 = 4.15888308336f*4.15888308336f
                           + 3.46573590280f*3.46573590280f
                           + 2.77258872224f*2.77258872224f
                           + 2.07944154168f*2.07944154168f
                           + 1.38629436112f*1.38629436112f;
            out[gi * OH + wj] = -(part + other) / S2;
        }
    }
}

extern "C" void kernel_launch(void* const* d_in, const int* in_sizes, int n_in,
                              void* d_out, int out_size)
{
    const float* img = (const float*)d_in[0];   // (1,1,512,512) f32
    float* out = (float*)d_out;                 // (1,1,113,113) f32
    fd_kernel<<<OH, 1024>>>(img, out);
}